// round 12
// baseline (speedup 1.0000x reference)
#include <cuda_runtime.h>
#include <cuda_bf16.h>
#include <cuda_fp16.h>
#include <cstdint>

#define T_TOK 8192
#define H_DIM 2048
#define I_DIM 1408
#define E_NUM 8
#define NI2   (2 * I_DIM)   // 2816 interleaved gate/up columns
#define CAP   8192          // max rows per expert (top-2 of distinct experts)
#define WSCALE 64.0f
#define WINV   (1.0f / 64.0f)

// ---------------- scratch (device globals; no allocations) ----------------
__device__ int   d_count[E_NUM];                 // zero at load; re-zeroed by k_combine
__device__ float d_tok_w[T_TOK * 2];
__device__ int   d_pos[T_TOK * 2];               // token,k -> row in per-expert region
__device__ int   d_pair_slot[E_NUM * CAP];       // row -> tok*2+k

__device__ __align__(16) __half d_xh[(size_t)T_TOK * H_DIM];                 // x fp16
__device__ __align__(16) __half d_w1hi[(size_t)E_NUM * NI2 * H_DIM];         // W1*64 fp16
__device__ __align__(16) __half d_w2hi[(size_t)E_NUM * H_DIM * I_DIM];       // W2^T*64 fp16
__device__ __align__(16) __half d_h[(size_t)E_NUM * CAP * I_DIM];            // activations fp16
__device__ __align__(16) float  d_y[(size_t)E_NUM * CAP * H_DIM];

// ---------------- helpers ----------------
static __device__ __forceinline__ uint32_t smem_u32(const void* p) {
    return (uint32_t)__cvta_generic_to_shared(p);
}
static __device__ __forceinline__ void ldsm4(uint32_t& r0, uint32_t& r1, uint32_t& r2, uint32_t& r3, uint32_t a) {
    asm volatile("ldmatrix.sync.aligned.m8n8.x4.shared.b16 {%0,%1,%2,%3},[%4];"
                 : "=r"(r0), "=r"(r1), "=r"(r2), "=r"(r3) : "r"(a));
}
static __device__ __forceinline__ void mma_fp16(float* c, const uint32_t* a, const uint32_t* b) {
    asm volatile("mma.sync.aligned.m16n8k16.row.col.f32.f16.f16.f32 "
                 "{%0,%1,%2,%3},{%4,%5,%6,%7},{%8,%9},{%0,%1,%2,%3};"
                 : "+f"(c[0]), "+f"(c[1]), "+f"(c[2]), "+f"(c[3])
                 : "r"(a[0]), "r"(a[1]), "r"(a[2]), "r"(a[3]), "r"(b[0]), "r"(b[1]));
}
static __device__ __forceinline__ void cpa16(uint32_t s, const void* g, int sz) {
    asm volatile("cp.async.cg.shared.global [%0], [%1], 16, %2;" :: "r"(s), "l"(g), "r"(sz));
}

// GEMM smem geometry: A 128 rows + B 256 rows, 64 halfs per row, 144B pitch
#define PITCH2      144
#define A_BYTES     (128 * PITCH2)            // 18432
#define B_BYTES     (256 * PITCH2)            // 36864
#define STAGE2      (A_BYTES + B_BYTES)       // 55296
#define SMEM2       (512 + 2 * STAGE2)        // 111104

// ---------------- launch 1: router (fused compaction via per-expert capacity) ----------------
__global__ void k_router(const float* __restrict__ x, const float* __restrict__ gw) {
    int warp = (blockIdx.x * blockDim.x + threadIdx.x) >> 5;
    int lane = threadIdx.x & 31;
    if (warp >= T_TOK) return;
    const float* xr = x + (size_t)warp * H_DIM;
    float acc[E_NUM];
#pragma unroll
    for (int e = 0; e < E_NUM; e++) acc[e] = 0.f;
    for (int i = lane; i < H_DIM; i += 32) {
        float xv = xr[i];
#pragma unroll
        for (int e = 0; e < E_NUM; e++) acc[e] += xv * gw[e * H_DIM + i];
    }
#pragma unroll
    for (int e = 0; e < E_NUM; e++)
#pragma unroll
        for (int o = 16; o > 0; o >>= 1) acc[e] += __shfl_xor_sync(0xffffffffu, acc[e], o);
    if (lane == 0) {
        float m = acc[0];
#pragma unroll
        for (int e = 1; e < E_NUM; e++) m = fmaxf(m, acc[e]);
        float p[E_NUM];
#pragma unroll
        for (int e = 0; e < E_NUM; e++) p[e] = __expf(acc[e] - m);
        int e0 = 0; float w0 = p[0];
#pragma unroll
        for (int e = 1; e < E_NUM; e++) if (p[e] > w0) { w0 = p[e]; e0 = e; }
        int e1 = -1; float w1 = -1.f;
#pragma unroll
        for (int e = 0; e < E_NUM; e++) if (e != e0 && p[e] > w1) { w1 = p[e]; e1 = e; }
        float inv = 1.f / (w0 + w1);
        d_tok_w[warp * 2 + 0] = w0 * inv;
        d_tok_w[warp * 2 + 1] = w1 * inv;
        int p0 = e0 * CAP + atomicAdd(&d_count[e0], 1);
        int p1 = e1 * CAP + atomicAdd(&d_count[e1], 1);
        d_pair_slot[p0] = warp * 2 + 0;  d_pos[warp * 2 + 0] = p0;
        d_pair_slot[p1] = warp * 2 + 1;  d_pos[warp * 2 + 1] = p1;
    }
}

// ---------------- launch 2: x -> fp16 ----------------
__global__ void k_convx(const float* __restrict__ x) {
    size_t idx = (size_t)blockIdx.x * 256 + threadIdx.x;        // one float4
    float4 v = ((const float4*)x)[idx];
    ((__half2*)d_xh)[2 * idx + 0] = __floats2half2_rn(v.x, v.y);
    ((__half2*)d_xh)[2 * idx + 1] = __floats2half2_rn(v.z, v.w);
}

// ---------------- launch 3: W1 transpose+interleave -> [e][2i+mat][H], *64, fp16 ----------------
__global__ void k_w1t(const float* __restrict__ wg, const float* __restrict__ wu) {
    __shared__ float tile[32][33];
    int mat = blockIdx.z & 1, e = blockIdx.z >> 1;
    const float* src = (mat ? wu : wg) + (size_t)e * H_DIM * I_DIM;
    int i0 = blockIdx.x * 32, h0 = blockIdx.y * 32;
    int tx = threadIdx.x, ty = threadIdx.y;
#pragma unroll
    for (int j = 0; j < 4; j++)
        tile[ty + 8 * j][tx] = src[(size_t)(h0 + ty + 8 * j) * I_DIM + i0 + tx];
    __syncthreads();
#pragma unroll
    for (int j = 0; j < 4; j++) {
        int oi = i0 + ty + 8 * j, oh = h0 + tx;
        float v = tile[tx][ty + 8 * j] * WSCALE;
        size_t o = ((size_t)e * NI2 + 2 * oi + mat) * H_DIM + oh;
        d_w1hi[o] = __float2half_rn(v);
    }
}

// ---------------- launch 5: Wdown transpose -> [e][h][i], *64, fp16 ----------------
__global__ void k_w2t(const float* __restrict__ wd) {
    __shared__ float tile[32][33];
    int e = blockIdx.z;
    const float* src = wd + (size_t)e * I_DIM * H_DIM;
    int h0 = blockIdx.x * 32, i0 = blockIdx.y * 32;
    int tx = threadIdx.x, ty = threadIdx.y;
#pragma unroll
    for (int j = 0; j < 4; j++)
        tile[ty + 8 * j][tx] = src[(size_t)(i0 + ty + 8 * j) * H_DIM + h0 + tx];
    __syncthreads();
#pragma unroll
    for (int j = 0; j < 4; j++) {
        int oh = h0 + ty + 8 * j, oi = i0 + tx;
        float v = tile[tx][ty + 8 * j] * WSCALE;
        size_t o = ((size_t)e * H_DIM + oh) * I_DIM + oi;
        d_w2hi[o] = __float2half_rn(v);
    }
}

// ---------------- 64-K compute slab, warp tile 64x64 (8 warps over 128x256) ----------------
#define COMPUTE_SLAB64(pA, pB)                                                          \
    _Pragma("unroll")                                                                   \
    for (int kk = 0; kk < 64; kk += 16) {                                               \
        uint32_t afr[4][4], bh[8][2];                                                   \
        _Pragma("unroll")                                                               \
        for (int p = 0; p < 4; p++) {                                                   \
            int bn = wn + p * 16 + ((lane >> 4) << 3) + (lane & 7);                     \
            int bk = kk + ((lane >> 3) & 1) * 8;                                        \
            uint32_t r0, r1, r2, r3;                                                    \
            ldsm4(r0, r1, r2, r3, smem_u32(pB + bn * PITCH2 + bk * 2));                 \
            bh[p * 2][0] = r0; bh[p * 2][1] = r1;                                       \
            bh[p * 2 + 1][0] = r2; bh[p * 2 + 1][1] = r3;                               \
        }                                                                               \
        _Pragma("unroll")                                                               \
        for (int mi = 0; mi < 4; mi++) {                                                \
            int row = wm + mi * 16 + (lane & 15);                                       \
            int col = kk + (lane >> 4) * 8;                                             \
            ldsm4(afr[mi][0], afr[mi][1], afr[mi][2], afr[mi][3],                       \
                  smem_u32(pA + row * PITCH2 + col * 2));                               \
        }                                                                               \
        _Pragma("unroll")                                                               \
        for (int mi = 0; mi < 4; mi++)                                                  \
            _Pragma("unroll")                                                           \
            for (int ni = 0; ni < 8; ni++)                                              \
                mma_fp16(acc[mi][ni], afr[mi], bh[ni]);                                 \
    }

// ---------------- launch 4 (PROFILED): GEMM1 gathered X @ [Wgate ⧉ Wup]*64 -> h ----------------
__global__ void __launch_bounds__(256, 1) k_gemm1() {
    extern __shared__ char smem[];
    int e = blockIdx.z;
    int cnt = d_count[e];
    int rowbase = blockIdx.y * 128;
    if (rowbase >= cnt) return;
    int off = e * CAP, ct = blockIdx.x;
    int tid = threadIdx.x, warp = tid >> 5, lane = tid & 31;
    int wm = (warp & 1) * 64, wn = (warp >> 1) * 64;

    int* sTok = (int*)smem;
    if (tid < 128) {
        int gr = rowbase + tid;
        sTok[tid] = (gr < cnt) ? (d_pair_slot[off + gr] >> 1) : -1;
    }
    __syncthreads();

    const __half* wbH = d_w1hi + ((size_t)e * NI2 + (size_t)ct * 256) * H_DIM;

    float acc[4][8][4];
#pragma unroll
    for (int mi = 0; mi < 4; mi++)
#pragma unroll
        for (int ni = 0; ni < 8; ni++)
#pragma unroll
            for (int j = 0; j < 4; j++) acc[mi][ni][j] = 0.f;

    const int NKB = H_DIM / 64;   // 32
    auto issue = [&](int kb) {
        char* st = smem + 512 + (size_t)(kb & 1) * STAGE2;
        int k0 = kb * 64;
#pragma unroll
        for (int i = 0; i < 12; i++) {
            int idx = tid + i * 256;
            const __half* g; int sz = 16;
            uint32_t sa;
            if (idx < 1024) {            // A: 128 rows x 8 cols
                int r = idx >> 3, c = idx & 7;
                sa = smem_u32(st + r * PITCH2 + c * 16);
                int tok = sTok[r];
                if (tok < 0) { tok = 0; sz = 0; }
                g = d_xh + (size_t)tok * H_DIM + k0 + c * 8;
            } else {                     // B: 256 rows x 8 cols
                int j = idx - 1024;
                int r = j >> 3, c = j & 7;
                sa = smem_u32(st + A_BYTES + r * PITCH2 + c * 16);
                g = wbH + (size_t)r * H_DIM + k0 + c * 8;
            }
            cpa16(sa, g, sz);
        }
        asm volatile("cp.async.commit_group;");
    };

    issue(0);
    for (int kb = 0; kb < NKB; kb++) {
        asm volatile("cp.async.wait_group 0;" ::: "memory");
        __syncthreads();
        if (kb + 1 < NKB) issue(kb + 1);
        char* st = smem + 512 + (size_t)(kb & 1) * STAGE2;
        char* pA = st;
        char* pB = st + A_BYTES;
        COMPUTE_SLAB64(pA, pB);
    }

    // epilogue: (c0,c1) = (gate, up)*64 at same h column; unscale BEFORE silu
#pragma unroll
    for (int mi = 0; mi < 4; mi++) {
        int gr0 = rowbase + wm + mi * 16 + (lane >> 2);
        int gr1 = gr0 + 8;
#pragma unroll
        for (int ni = 0; ni < 8; ni++) {
            int ncol = wn + ni * 8 + (lane & 3) * 2;
            int hc = ct * 128 + (ncol >> 1);
            if (gr0 < cnt) {
                float g = acc[mi][ni][0] * WINV, u = acc[mi][ni][1] * WINV;
                float y = u * g / (1.f + __expf(-g));
                d_h[(size_t)(off + gr0) * I_DIM + hc] = __float2half_rn(y);
            }
            if (gr1 < cnt) {
                float g = acc[mi][ni][2] * WINV, u = acc[mi][ni][3] * WINV;
                float y = u * g / (1.f + __expf(-g));
                d_h[(size_t)(off + gr1) * I_DIM + hc] = __float2half_rn(y);
            }
        }
    }
}

// ---------------- launch 6: GEMM2 h @ (Wdown*64)^T -> y ----------------
__global__ void __launch_bounds__(256, 1) k_gemm2() {
    extern __shared__ char smem[];
    int e = blockIdx.z;
    int cnt = d_count[e];
    int rowbase = blockIdx.y * 128;
    if (rowbase >= cnt) return;
    int off = e * CAP, nt = blockIdx.x;
    int tid = threadIdx.x, warp = tid >> 5, lane = tid & 31;
    int wm = (warp & 1) * 64, wn = (warp >> 1) * 64;

    const __half* wbH = d_w2hi + ((size_t)e * H_DIM + (size_t)nt * 256) * I_DIM;
    const __half* aH0 = d_h + (size_t)(off + rowbase) * I_DIM;

    float acc[4][8][4];
#pragma unroll
    for (int mi = 0; mi < 4; mi++)
#pragma unroll
        for (int ni = 0; ni < 8; ni++)
#pragma unroll
            for (int j = 0; j < 4; j++) acc[mi][ni][j] = 0.f;

    const int NKB = I_DIM / 64;   // 22
    auto issue = [&](int kb) {
        char* st = smem + 512 + (size_t)(kb & 1) * STAGE2;
        int k0 = kb * 64;
#pragma unroll
        for (int i = 0; i < 12; i++) {
            int idx = tid + i * 256;
            const __half* g; int sz = 16;
            uint32_t sa;
            if (idx < 1024) {            // A: 128 rows x 8 cols
                int r = idx >> 3, c = idx & 7;
                sa = smem_u32(st + r * PITCH2 + c * 16);
                if (rowbase + r >= cnt) sz = 0;
                g = aH0 + (size_t)r * I_DIM + k0 + c * 8;
            } else {                     // B: 256 rows x 8 cols
                int j = idx - 1024;
                int r = j >> 3, c = j & 7;
                sa = smem_u32(st + A_BYTES + r * PITCH2 + c * 16);
                g = wbH + (size_t)r * I_DIM + k0 + c * 8;
            }
            cpa16(sa, g, sz);
        }
        asm volatile("cp.async.commit_group;");
    };

    issue(0);
    for (int kb = 0; kb < NKB; kb++) {
        asm volatile("cp.async.wait_group 0;" ::: "memory");
        __syncthreads();
        if (kb + 1 < NKB) issue(kb + 1);
        char* st = smem + 512 + (size_t)(kb & 1) * STAGE2;
        char* pA = st;
        char* pB = st + A_BYTES;
        COMPUTE_SLAB64(pA, pB);
    }

#pragma unroll
    for (int mi = 0; mi < 4; mi++) {
        int gr0 = rowbase + wm + mi * 16 + (lane >> 2);
        int gr1 = gr0 + 8;
#pragma unroll
        for (int ni = 0; ni < 8; ni++) {
            int col = nt * 256 + wn + ni * 8 + (lane & 3) * 2;
            if (gr0 < cnt) {
                float2 v = make_float2(acc[mi][ni][0] * WINV, acc[mi][ni][1] * WINV);
                *(float2*)&d_y[(size_t)(off + gr0) * H_DIM + col] = v;
            }
            if (gr1 < cnt) {
                float2 v = make_float2(acc[mi][ni][2] * WINV, acc[mi][ni][3] * WINV);
                *(float2*)&d_y[(size_t)(off + gr1) * H_DIM + col] = v;
            }
        }
    }
}

// ---------------- launch 7: combine + re-zero counters for next replay ----------------
__global__ void k_combine(float* __restrict__ out) {
    if (blockIdx.x == 0 && threadIdx.x < E_NUM) d_count[threadIdx.x] = 0;
    size_t idx = (size_t)blockIdx.x * 256 + threadIdx.x;   // one float4 of out
    const int H4 = H_DIM / 4;
    int t = (int)(idx / H4);
    int c = (int)(idx % H4);
    int p0 = d_pos[2 * t], p1 = d_pos[2 * t + 1];
    float w0 = d_tok_w[2 * t], w1 = d_tok_w[2 * t + 1];
    const float4* y = (const float4*)d_y;
    float4 a = y[(size_t)p0 * H4 + c];
    float4 b = y[(size_t)p1 * H4 + c];
    float4 o;
    o.x = w0 * a.x + w1 * b.x;
    o.y = w0 * a.y + w1 * b.y;
    o.z = w0 * a.z + w1 * b.z;
    o.w = w0 * a.w + w1 * b.w;
    ((float4*)out)[idx] = o;
}

// ---------------- launch ----------------
extern "C" void kernel_launch(void* const* d_in, const int* in_sizes, int n_in,
                              void* d_out, int out_size) {
    const float* x  = (const float*)d_in[0];   // [T, H]
    const float* gw = (const float*)d_in[1];   // [E, H]
    const float* wg = (const float*)d_in[2];   // [E, H, I]
    const float* wu = (const float*)d_in[3];   // [E, H, I]
    const float* wd = (const float*)d_in[4];   // [E, I, H]
    float* out = (float*)d_out;                // [T, H]

    cudaFuncSetAttribute(k_gemm1, cudaFuncAttributeMaxDynamicSharedMemorySize, SMEM2);
    cudaFuncSetAttribute(k_gemm2, cudaFuncAttributeMaxDynamicSharedMemorySize, SMEM2);

    k_router<<<T_TOK / 8, 256>>>(x, gw);                                     // 1
    k_convx<<<(int)((size_t)T_TOK * H_DIM / 4 / 256), 256>>>(x);             // 2
    k_w1t<<<dim3(I_DIM / 32, H_DIM / 32, E_NUM * 2), dim3(32, 8)>>>(wg, wu); // 3
    k_gemm1<<<dim3(NI2 / 256, CAP / 128, E_NUM), 256, SMEM2>>>();            // 4 <- profiled
    k_w2t<<<dim3(H_DIM / 32, I_DIM / 32, E_NUM), dim3(32, 8)>>>(wd);         // 5
    k_gemm2<<<dim3(H_DIM / 256, CAP / 128, E_NUM), 256, SMEM2>>>();          // 6
    k_combine<<<(int)((size_t)T_TOK * H_DIM / 4 / 256), 256>>>(out);         // 7
}